// round 7
// baseline (speedup 1.0000x reference)
#include <cuda_runtime.h>
#include <math.h>

#define NMODES 6400
#define MMAX 80
#define GROUPS 25          // NMODES / 256
#define GSZ 256
#define SCHUNK 64          // samples per plate block
#define SH 32              // SCHUNK/2 packed f32x2 accumulators
#define NCB 1024           // bucket table size (chunks); N=44100 -> 690 chunks

typedef unsigned long long u64;

// ---------------- static device scratch (no runtime allocation) -------------
__device__ float4 gA0[NMODES], gB0[NMODES];   // staging (mode-index order)
__device__ float4 gA[NMODES],  gB[NMODES];    // sorted by lifetime desc
__device__ int    gLc[NMODES];                // live-chunk count per mode
__device__ int    gRank[NMODES];              // deterministic rank in (group,bucket)
__device__ int    gH[GROUPS][NCB];            // per-group bucket histograms
__device__ int    gBase[NCB];                 // bucket base = live count L(c)
__device__ unsigned int gPeakBits;
__device__ int    gSync = 0;                  // block-arrival counter
__device__ int    gFlag = 0;                  // bases-ready flag

// ---------------- f32x2 packed helpers (Blackwell FFMA2 path) ---------------
__device__ __forceinline__ u64 pack2(float lo, float hi) {
    u64 r; asm("mov.b64 %0, {%1, %2};" : "=l"(r) : "f"(lo), "f"(hi)); return r;
}
__device__ __forceinline__ u64 fma2(u64 a, u64 b, u64 c) {
    u64 d; asm("fma.rn.f32x2 %0, %1, %2, %3;" : "=l"(d) : "l"(a), "l"(b), "l"(c)); return d;
}
__device__ __forceinline__ u64 mul2(u64 a, u64 b) {
    u64 d; asm("mul.rn.f32x2 %0, %1, %2;" : "=l"(d) : "l"(a), "l"(b)); return d;
}
__device__ __forceinline__ u64 add2(u64 a, u64 b) {
    u64 d; asm("add.rn.f32x2 %0, %1, %2;" : "=l"(d) : "l"(a), "l"(b)); return d;
}

__device__ __forceinline__ float softplusf(float x) {
    return (x > 20.0f) ? x : log1pf(expf(x));
}

// ---------------------------------------------------------------------------
// Fused setup: per-mode precompute + histogram/rank + (last block) suffix
// scan + all-block scatter.  grid = 25 x 256 (always one wave -> spin safe).
// ---------------------------------------------------------------------------
__global__ void __launch_bounds__(GSZ) setup_kernel(
    const float* __restrict__ pmu, const float* __restrict__ pD,
    const float* __restrict__ pT0, const float* __restrict__ pLy,
    const float* __restrict__ pxo, const float* __restrict__ pyo, int NC)
{
    const int g = blockIdx.x, t = threadIdx.x;
    const int i = g * GSZ + t;
    const int warp = t >> 5, lane = t & 31;

    float mu   = softplusf(pmu[0]) + 1e-4f;
    float Dmu  = softplusf(pD[0])  + 1e-4f;
    float T0mu = softplusf(pT0[0]) + 1e-4f;
    float Ly = 1.1f + (4.0f - 1.1f) * ((tanhf(pLy[0]) + 1.0f) * 0.5f);
    const float LX = 0.5f;
    float xo = 0.49f * LX + (1.0f - 0.49f) * LX * ((tanhf(pxo[0]) + 1.0f) * 0.5f);
    float yo = 0.51f * Ly + (1.0f - 0.51f) * Ly * ((tanhf(pyo[0]) + 1.0f) * 0.5f);

    const float PI  = 3.14159265358979323846f;
    const float Kf  = (float)(1.0 / 44100.0);
    const float MAXOM = (float)(10000.0 * 2.0 * 3.141592653589793);
    const float MINOM = (float)(20.0 * 2.0 * 3.141592653589793);
    const double OM2   = 2.0 * 3.141592653589793 * 500.0;
    const double DOMSQ = OM2 * OM2;
    const double LN10T3 = 3.0 * 2.302585092994045684;
    const float ALPHA = (float)(LN10T3 / DOMSQ * (DOMSQ / 6.0));
    const float BETA  = (float)(LN10T3 / DOMSQ * (1.0 / 1.0 - 1.0 / 6.0));

    float m  = (float)(i / MMAX + 1);
    float nn = (float)(i % MMAX + 1);

    // omega / validity path identical (fp32) to the known-passing kernel
    float t1 = (m * PI) / LX;
    float t2 = (nn * PI) / Ly;
    float g1 = t1 * t1 + t2 * t2;
    float w2 = T0mu * g1 + (Dmu * g1) * g1;
    w2 = fmaxf(w2, 0.0f);
    float omega = sqrtf(w2);
    int valid = (omega <= MAXOM) && (omega >= MINOM);

    float sigma = ALPHA + BETA * (omega * omega);
    float xi = 0.1f * LX, yi = 0.1f * Ly;
    float in_w  = cosf(((xi * PI) * m) / LX) * cosf(((yi * PI) * nn) / Ly);
    float out_w = cosf(((xo * PI) * m) / LX) * cosf(((yo * PI) * nn) / Ly);
    float ms = 0.25f * mu * LX * Ly;
    float P  = out_w * in_w * (Kf * Kf) * expf(-sigma * Kf) / ms;

    float thK  = omega * Kf;
    float sigK = sigma * Kf;

    float sth, cth;
    sincosf(thK, &sth, &cth);
    float r   = expf(-sigK);
    float r2  = r * r;
    float c2  = fmaf(-2.0f * sth, sth, 1.0f);   // cos(2*thK) = 1 - 2 sin^2
    float a2  = 2.0f * r2 * c2;
    float nb2 = -(r2 * r2);
    float C   = P / (sth + 1e-8f);

    float cutoff = 20.0f / sigK;                // live while sigK*(n-1) <= 20
    int lc = 0;
    if (valid) {
        lc = (int)floorf((cutoff + 1.0f) / 64.0f) + 1;
        lc = max(0, min(lc, min(NC, NCB - 1)));
    }

    gA0[i] = make_float4(a2, nb2, C, cutoff);
    gB0[i] = make_float4(thK, sth, cth, sigK);
    gLc[i] = lc;

    // deterministic rank within (group,bucket): match-any within warp,
    // fixed warp order across warps
    __shared__ int sh_h[NCB];
    for (int b = t; b < NCB; b += GSZ) sh_h[b] = 0;
    __syncthreads();

    unsigned msk = __match_any_sync(0xFFFFFFFFu, lc);
    int riw    = __popc(msk & ((1u << lane) - 1u));
    int leader = __ffs(msk) - 1;
    int cnt    = __popc(msk);
    int rk = 0;
    #pragma unroll
    for (int w = 0; w < 8; ++w) {
        if (warp == w) {
            int base = 0;
            if (lane == leader) base = atomicAdd(&sh_h[lc], cnt);
            base = __shfl_sync(0xFFFFFFFFu, base, leader);
            rk = base + riw;
        }
        __syncthreads();
    }
    gRank[i] = rk;
    for (int b = t; b < NCB; b += GSZ) gH[g][b] = sh_h[b];

    if (g == 0 && t == 0) gPeakBits = 0u;

    // ---- arrival: last block computes suffix-sum bases -----------------
    __shared__ int sh_last;
    __threadfence();
    __syncthreads();
    if (t == 0) sh_last = (atomicAdd(&gSync, 1) == GROUPS - 1);
    __syncthreads();

    if (sh_last) {
        const int NB = min(NC, NCB - 1);        // max bucket index
        __shared__ int tot[NCB];
        __shared__ int tsum[GSZ];
        for (int b = t; b < NCB; b += GSZ) {
            int s = 0;
            #pragma unroll
            for (int g2 = 0; g2 < GROUPS; ++g2) s += gH[g2][b];
            tot[b] = s;
        }
        __syncthreads();
        // suffix sum over b == exclusive prefix over reversed index r = NB - b
        int loc[4]; int run = 0;
        #pragma unroll
        for (int k = 0; k < 4; ++k) {
            int rr = 4 * t + k;
            int v = (rr <= NB) ? tot[NB - rr] : 0;
            loc[k] = run; run += v;
        }
        tsum[t] = run;
        __syncthreads();
        #pragma unroll
        for (int off = 1; off < GSZ; off <<= 1) {
            int v = (t >= off) ? tsum[t - off] : 0;
            __syncthreads();
            tsum[t] += v;
            __syncthreads();
        }
        int base0 = (t == 0) ? 0 : tsum[t - 1];
        #pragma unroll
        for (int k = 0; k < 4; ++k) {
            int rr = 4 * t + k;
            if (rr <= NB) gBase[NB - rr] = base0 + loc[k];
        }
        __threadfence();
        __syncthreads();
        if (t == 0) gFlag = 1;
    }

    // ---- all blocks: wait for bases, then scatter own modes ------------
    if (t == 0) { while (0 == *((volatile int*)&gFlag)) {} }
    __syncthreads();
    __threadfence();

    int lcv = lc;
    int pos = gBase[lcv] + rk;
    for (int g2 = 0; g2 < g; ++g2) pos += gH[g2][lcv];
    gA[pos] = gA0[i];
    gB[pos] = gB0[i];
}

// ---------------------------------------------------------------------------
// Plate: one block per 64-sample chunk; exactly the live modes (sorted
// prefix). FOUR independent mode chains per thread for FMA-latency ILP.
// ---------------------------------------------------------------------------
struct Chain { u64 vc, vp, A2, nB2; };

__device__ __forceinline__ Chain seed_chain(float4 A, float4 B,
                                            float n0f, float n0m1, bool on)
{
    float s0, c0;
    sincosf(n0f * B.x, &s0, &c0);               // accurate phase re-seed
    float E0   = __expf(-B.w * n0m1);
    float r    = __expf(-B.w);
    float rinv = __expf(B.w);

    float sp1 = fmaf(s0, B.z,  c0 * B.y);       // sin((n0+1)θ)
    float sm1 = fmaf(s0, B.z, -c0 * B.y);       // sin((n0-1)θ)
    float sm2 = fmaf(2.0f * B.z, sm1, -s0);     // sin((n0-2)θ)

    float CE = on ? (A.z * E0) : 0.0f;
    Chain ch;
    ch.vc  = pack2(CE * s0, CE * r * sp1);                     // y(n0), y(n0+1)
    ch.vp  = pack2(CE * (rinv * rinv) * sm2, CE * rinv * sm1); // y(n0-2), y(n0-1)
    ch.A2  = pack2(A.x, A.x);
    ch.nB2 = pack2(A.y, A.y);
    return ch;
}

__global__ void __launch_bounds__(256, 2) plate_kernel(float* __restrict__ out, int N)
{
    const int lane = threadIdx.x & 31;
    const int warp = threadIdx.x >> 5;
    const int c    = blockIdx.x;
    const int n0   = c * SCHUNK;
    const float n0f  = (float)n0;
    const float n0m1 = n0f - 1.0f;
    const int Lc = gBase[c];                    // live modes = sorted prefix

    u64 acc[SH];
    #pragma unroll
    for (int j = 0; j < SH; ++j) acc[j] = 0ull;

    #pragma unroll 1
    for (int i = threadIdx.x; i < Lc; i += 1024) {
        Chain ch[4];
        #pragma unroll
        for (int k = 0; k < 4; ++k) {
            int idx = i + k * 256;
            bool on = idx < Lc;
            int ic = on ? idx : (Lc - 1);       // duplicate w/ CE=0 past end
            ch[k] = seed_chain(gA[ic], gB[ic], n0f, n0m1, on);
        }

        acc[0] = add2(acc[0], add2(add2(ch[0].vc, ch[1].vc),
                                   add2(ch[2].vc, ch[3].vc)));
        #pragma unroll
        for (int j = 1; j < SH; ++j) {
            u64 n_[4];
            #pragma unroll
            for (int k = 0; k < 4; ++k) {
                u64 mm = mul2(ch[k].nB2, ch[k].vp);
                n_[k] = fma2(ch[k].A2, ch[k].vc, mm);
                ch[k].vp = ch[k].vc; ch[k].vc = n_[k];
            }
            acc[j] = add2(acc[j], add2(add2(n_[0], n_[1]), add2(n_[2], n_[3])));
        }
    }

    // warp transpose-reduce: lane l ends owning sample pair (2l, 2l+1)
    #pragma unroll
    for (int stage = 0; stage < 5; ++stage) {
        const int d = 16 >> stage;
        const bool hi = (lane & d) != 0;
        #pragma unroll
        for (int j = 0; j < (16 >> stage); ++j) {
            const int mm = 16 >> stage;
            u64 a_ = acc[j], b_ = acc[j + mm];
            u64 send = hi ? a_ : b_;
            u64 keep = hi ? b_ : a_;
            u64 recv = __shfl_xor_sync(0xFFFFFFFFu, send, d);
            acc[j] = add2(keep, recv);
        }
    }

    __shared__ u64 sred[8][33];
    sred[warp][lane] = acc[0];
    __syncthreads();

    if (threadIdx.x < SCHUNK) {
        const int j = threadIdx.x;
        const float* f = (const float*)sred;    // row stride = 66 floats
        float v = 0.0f;
        #pragma unroll
        for (int w = 0; w < 8; ++w) v += f[w * 66 + j];

        int sample = n0 + j;
        float av = fabsf(v);
        if (sample < N) out[sample] = v; else av = 0.0f;
        #pragma unroll
        for (int o = 16; o > 0; o >>= 1)
            av = fmaxf(av, __shfl_xor_sync(0xFFFFFFFFu, av, o));
        if (lane == 0) atomicMax(&gPeakBits, __float_as_uint(av));
    }
}

// ---------------------------------------------------------------------------
// Scale + reset of sync state for next replay (runs last -> replay-safe)
// ---------------------------------------------------------------------------
__global__ void scale_kernel(float* __restrict__ out, int N)
{
    int i = blockIdx.x * blockDim.x + threadIdx.x;
    if (i == 0) { gSync = 0; gFlag = 0; }
    if (i < N) {
        float peak = __uint_as_float(gPeakBits) + 1e-8f;
        out[i] = out[i] / peak;
    }
}

// ---------------------------------------------------------------------------
extern "C" void kernel_launch(void* const* d_in, const int* in_sizes, int n_in,
                              void* d_out, int out_size)
{
    const float* mu  = (const float*)d_in[0];
    const float* Dm  = (const float*)d_in[1];
    const float* T0m = (const float*)d_in[2];
    const float* Lyr = (const float*)d_in[3];
    const float* xr  = (const float*)d_in[4];
    const float* yr  = (const float*)d_in[5];
    int N  = out_size;                          // == num_samples
    int NC = (N + SCHUNK - 1) / SCHUNK;
    float* out = (float*)d_out;

    setup_kernel<<<GROUPS, GSZ>>>(mu, Dm, T0m, Lyr, xr, yr, NC);
    plate_kernel<<<NC, 256>>>(out, N);
    scale_kernel<<<(N + 255) / 256, 256>>>(out, N);
}